// round 8
// baseline (speedup 1.0000x reference)
#include <cuda_runtime.h>
#include <math.h>
#include <stdint.h>

// Problem constants
#define BATCH 4
#define TLEN  1024
#define EDIM  1024
#define HEADS 16
#define SDIM  64
#define P2    2047   // 2*t - 1

// ---------------------------------------------------------------------------
// Scratch (device globals — no runtime allocation allowed)
// ---------------------------------------------------------------------------
__device__ float g_Q  [(size_t)BATCH * TLEN * EDIM];
__device__ float g_K  [(size_t)BATCH * TLEN * EDIM];
__device__ float g_V  [(size_t)BATCH * TLEN * EDIM];
__device__ float g_KP [(size_t)P2 * EDIM];
__device__ float g_dpt[(size_t)BATCH * HEADS * TLEN];
__device__ float g_cpp[(size_t)HEADS * P2];
__device__ float g_ATT[(size_t)BATCH * TLEN * EDIM];
__device__ float g_Wt [(size_t)5 * EDIM * EDIM];   // transposed weights [N,K]

// ---------------------------------------------------------------------------
// tf32 helpers. Mask split: hi = x with low 13 bits zeroed (tf32-exact),
// lo = x - hi exact in fp32 (Sterbenz).
// ---------------------------------------------------------------------------
__device__ __forceinline__ void msplit(float x, uint32_t& hi, uint32_t& lo) {
    uint32_t h = __float_as_uint(x) & 0xFFFFE000u;
    hi = h;
    lo = __float_as_uint(x - __uint_as_float(h));
}
__device__ __forceinline__ float2 split2(float x) {
    float hi = __uint_as_float(__float_as_uint(x) & 0xFFFFE000u);
    return make_float2(hi, x - hi);
}
__device__ __forceinline__ void mma_tf32(float* c,
    uint32_t a0, uint32_t a1, uint32_t a2, uint32_t a3,
    uint32_t b0, uint32_t b1)
{
    asm volatile(
        "mma.sync.aligned.m16n8k8.row.col.f32.tf32.tf32.f32 "
        "{%0,%1,%2,%3}, {%4,%5,%6,%7}, {%8,%9}, {%0,%1,%2,%3};"
        : "+f"(c[0]), "+f"(c[1]), "+f"(c[2]), "+f"(c[3])
        : "r"(a0), "r"(a1), "r"(a2), "r"(a3), "r"(b0), "r"(b1));
}
// x3 compensated: al*bh + ah*bl + ah*bh (residual ~2^-22)
__device__ __forceinline__ void mma_x3(float* c,
    const uint32_t* ah, const uint32_t* al,
    uint32_t bh0, uint32_t bh1, uint32_t bl0, uint32_t bl1)
{
    mma_tf32(c, al[0], al[1], al[2], al[3], bh0, bh1);
    mma_tf32(c, ah[0], ah[1], ah[2], ah[3], bl0, bl1);
    mma_tf32(c, ah[0], ah[1], ah[2], ah[3], bh0, bh1);
}

// ---------------------------------------------------------------------------
// Batched weight transpose: dst[z][N,K] = src_z[K,N], 1024x1024 x5
// ---------------------------------------------------------------------------
__global__ void __launch_bounds__(256) transpose5_kernel(
    const float* __restrict__ W0, const float* __restrict__ W1,
    const float* __restrict__ W2, const float* __restrict__ W3,
    const float* __restrict__ W4, float* __restrict__ dstBase)
{
    __shared__ float t[32][33];
    int z = blockIdx.z;
    const float* src = (z == 0) ? W0 : (z == 1) ? W1 : (z == 2) ? W2
                     : (z == 3) ? W3 : W4;
    float* dst = dstBase + (size_t)z * EDIM * EDIM;
    int bx = blockIdx.x * 32, by = blockIdx.y * 32;
    int x = threadIdx.x, y = threadIdx.y;   // block (32, 8)
    #pragma unroll
    for (int i = 0; i < 32; i += 8)
        t[y + i][x] = src[(size_t)(by + y + i) * EDIM + bx + x];
    __syncthreads();
    #pragma unroll
    for (int i = 0; i < 32; i += 8)
        dst[(size_t)(bx + y + i) * EDIM + by + x] = t[x][y + i];
}

// ---------------------------------------------------------------------------
// Tensor-core GEMM tile body (tf32x3, PRE-SPLIT smem): C = A @ Bt^T (+bias)
// BK=32, 256 threads (8 warps: 64m x 32n each). Smem holds (hi,lo) float2;
// fragments are single LDS.64 (banks 8g+2t, conflict-free per half-warp).
// ---------------------------------------------------------------------------
#define GP 36
#define GEMM_SMEM_BYTES (2 * 128 * GP * 8)

__device__ __forceinline__ void gemm_tile(
    const float* __restrict__ A, const float* __restrict__ Bt,
    const float* __restrict__ bias, float* __restrict__ C,
    int M, int hasBias, int bm, int bn)
{
    extern __shared__ float2 gsm[];
    float2* A2 = gsm;              // [128][GP]
    float2* B2 = gsm + 128 * GP;   // [128][GP]

    const int tid  = threadIdx.x;
    const int wid  = tid >> 5;
    const int lane = tid & 31;
    const int wm = wid & 1;          // 0..1 : 64-row slice
    const int wn = wid >> 1;         // 0..3 : 32-col slice
    const int g = lane >> 2;         // group id 0..7
    const int t = lane & 3;          // thread-in-group 0..3

    const float4 f4z = make_float4(0.f, 0.f, 0.f, 0.f);
    float4 ra[4], rb[4];

    #pragma unroll
    for (int r = 0; r < 4; r++) {
        int slot = tid + 256 * r;
        int row = slot >> 3, kc = (slot & 7) * 4;
        int grow = bm + row;
        ra[r] = (grow < M) ? *(const float4*)&A[(size_t)grow * EDIM + kc] : f4z;
        rb[r] = *(const float4*)&Bt[(size_t)(bn + row) * EDIM + kc];
    }

    float acc[4][4][4];
    #pragma unroll
    for (int mi = 0; mi < 4; mi++)
        #pragma unroll
        for (int ni = 0; ni < 4; ni++)
            #pragma unroll
            for (int q = 0; q < 4; q++) acc[mi][ni][q] = 0.f;

    #pragma unroll 1
    for (int kt = 0; kt < 32; kt++) {
        __syncthreads();
        #pragma unroll
        for (int r = 0; r < 4; r++) {
            int slot = tid + 256 * r;
            int row = slot >> 3, kc = (slot & 7) * 4;
            float2* pa = &A2[row * GP + kc];
            float2* pb = &B2[row * GP + kc];
            pa[0] = split2(ra[r].x); pa[1] = split2(ra[r].y);
            pa[2] = split2(ra[r].z); pa[3] = split2(ra[r].w);
            pb[0] = split2(rb[r].x); pb[1] = split2(rb[r].y);
            pb[2] = split2(rb[r].z); pb[3] = split2(rb[r].w);
        }
        __syncthreads();

        if (kt + 1 < 32) {   // prefetch next k-tile
            int koff = (kt + 1) * 32;
            #pragma unroll
            for (int r = 0; r < 4; r++) {
                int slot = tid + 256 * r;
                int row = slot >> 3, kc = (slot & 7) * 4;
                int grow = bm + row;
                ra[r] = (grow < M) ? *(const float4*)&A[(size_t)grow * EDIM + koff + kc] : f4z;
                rb[r] = *(const float4*)&Bt[(size_t)(bn + row) * EDIM + koff + kc];
            }
        }

        #pragma unroll
        for (int kk = 0; kk < 32; kk += 8) {
            uint32_t ah[4][4], al[4][4];
            #pragma unroll
            for (int mi = 0; mi < 4; mi++) {
                int r0 = wm * 64 + mi * 16 + g;
                int c0 = kk + t;
                uint2 v0 = *(uint2*)&A2[r0 * GP + c0];
                uint2 v1 = *(uint2*)&A2[(r0 + 8) * GP + c0];
                uint2 v2 = *(uint2*)&A2[r0 * GP + c0 + 4];
                uint2 v3 = *(uint2*)&A2[(r0 + 8) * GP + c0 + 4];
                ah[mi][0] = v0.x; al[mi][0] = v0.y;
                ah[mi][1] = v1.x; al[mi][1] = v1.y;
                ah[mi][2] = v2.x; al[mi][2] = v2.y;
                ah[mi][3] = v3.x; al[mi][3] = v3.y;
            }
            #pragma unroll
            for (int ni = 0; ni < 4; ni++) {
                int rn = wn * 32 + ni * 8 + g;
                uint2 w0 = *(uint2*)&B2[rn * GP + kk + t];
                uint2 w1 = *(uint2*)&B2[rn * GP + kk + t + 4];
                #pragma unroll
                for (int mi = 0; mi < 4; mi++)
                    mma_x3(acc[mi][ni], ah[mi], al[mi], w0.x, w1.x, w0.y, w1.y);
            }
        }
    }

    #pragma unroll
    for (int mi = 0; mi < 4; mi++) {
        int row0 = bm + wm * 64 + mi * 16 + g;
        #pragma unroll
        for (int ni = 0; ni < 4; ni++) {
            int col = bn + wn * 32 + ni * 8 + t * 2;
            float b0 = hasBias ? bias[col] : 0.f;
            float b1 = hasBias ? bias[col + 1] : 0.f;
            if (row0 < M) {
                C[(size_t)row0 * EDIM + col]     = acc[mi][ni][0] + b0;
                C[(size_t)row0 * EDIM + col + 1] = acc[mi][ni][1] + b1;
            }
            if (row0 + 8 < M) {
                C[(size_t)(row0 + 8) * EDIM + col]     = acc[mi][ni][2] + b0;
                C[(size_t)(row0 + 8) * EDIM + col + 1] = acc[mi][ni][3] + b1;
            }
        }
    }
}

// Fused projections: z=0..2 -> Q/K/V from x; z=3 -> KP from pos_emb.
__global__ void __launch_bounds__(256, 2) fused_gemm_kernel(
    const float* __restrict__ x, const float* __restrict__ pos,
    const float* __restrict__ Wt0,
    float* __restrict__ Qb, float* __restrict__ Kb,
    float* __restrict__ Vb, float* __restrict__ KPb)
{
    const int z = blockIdx.z;
    const float* A = (z < 3) ? x : pos;
    const int M = (z < 3) ? (BATCH * TLEN) : P2;
    const int bm = blockIdx.y * 128;
    if (bm >= M) return;
    const float* Bt = Wt0 + (size_t)z * EDIM * EDIM;
    float* C = (z == 0) ? Qb : (z == 1) ? Kb : (z == 2) ? Vb : KPb;
    gemm_tile(A, Bt, nullptr, C, M, 0, bm, blockIdx.x * 128);
}

__global__ void __launch_bounds__(256, 2) gemmU_kernel(
    const float* __restrict__ A, const float* __restrict__ Bt,
    const float* __restrict__ bias, float* __restrict__ C)
{
    gemm_tile(A, Bt, bias, C, BATCH * TLEN, 1, blockIdx.y * 128, blockIdx.x * 128);
}

// ---------------------------------------------------------------------------
// Fused dpt + cpp
// ---------------------------------------------------------------------------
__global__ void __launch_bounds__(256) dptcpp_kernel(
    const float* __restrict__ Kt, const float* __restrict__ KP,
    const float* __restrict__ parma, const float* __restrict__ parmb,
    float* __restrict__ dpt, float* __restrict__ cpp)
{
    int idx = blockIdx.x * 256 + threadIdx.x;
    if (idx < BATCH * HEADS * TLEN) {
        int j = idx & (TLEN - 1);
        int h = (idx >> 10) & (HEADS - 1);
        int b = idx >> 14;
        const float* kr = Kt + ((size_t)(b * TLEN + j)) * EDIM + h * SDIM;
        const float* pa = parma + h * SDIM;
        float s = 0.f;
        #pragma unroll
        for (int ss = 0; ss < SDIM; ss++) s = fmaf(pa[ss], kr[ss], s);
        dpt[idx] = s;
    } else {
        int i2 = idx - BATCH * HEADS * TLEN;
        if (i2 >= HEADS * P2) return;
        int h = i2 / P2;
        int p = i2 - h * P2;
        const float* kr = KP + (size_t)p * EDIM + h * SDIM;
        const float* pb = parmb + h * SDIM;
        float s = 0.f;
        #pragma unroll
        for (int ss = 0; ss < SDIM; ss++) s = fmaf(pb[ss], kr[ss], s);
        cpp[i2] = s;
    }
}

// ---------------------------------------------------------------------------
// Tensor-core attention. One CTA per (b,h,64-row i-tile), 256 threads.
// Q pre-split (float2); V natural layout stride 72 (conflict-free staging
// AND PV reads); P written in place over S (no Psm buffer).
// ---------------------------------------------------------------------------
#define AP 68    // padded stride (fragment banks: scalar 4g+t, float2 8g+2t)
#define VP 72    // V stride: 72 % 32 == 8 -> PV banks 8t+g conflict-free
#define SP 196   // S matrix stride (64 rows x 192 cols)

#define ATTN_SMEM_FLOATS (64*AP*2 /*Qs2*/ + 192*AP /*Bs,Ssm*/ + 64*VP /*Vs*/ \
                        + 64 + 128 + 64 + 64)

__global__ void __launch_bounds__(256, 2) attn_kernel(
    const float* __restrict__ Q, const float* __restrict__ Kt,
    const float* __restrict__ V, const float* __restrict__ KP,
    const float* __restrict__ dpt, const float* __restrict__ cpp,
    float* __restrict__ O)
{
    extern __shared__ float sm[];
    float2* Qs2 = (float2*)sm;          // [64][AP]  pre-split Q (hi,lo)
    float*  Bs  = sm + 64 * AP * 2;     // [192][AP] K rows 0..63, KP band 64..191
    float*  Ssm = Bs;                   // [64][SP]  aliases Bs after scores mma
    float*  Vs  = Bs + 192 * AP;        // [64][VP]  natural: Vs[j][s]
    float*  dpts = Vs + 64 * VP;        // [64]
    float*  cpps = dpts + 64;           // [128]
    float*  scale_sm = cpps + 128;      // [64]
    float*  lsum_sm  = scale_sm + 64;   // [64]

    const int tid  = threadIdx.x;
    const int lane = tid & 31;
    const int wid  = tid >> 5;
    const int g = lane >> 2;            // 0..7
    const int t = lane & 3;             // 0..3
    const int rm = (wid & 1) * 32;      // scores m-base (32-row slice)
    const int cn = (wid >> 1) * 48;     // scores n-base (48-col slice)
    const int sm0 = (wid & 3) * 16;     // PV m-slice
    const int pn0 = (wid >> 2) * 32;    // PV n-slice
    const int tx = tid & 15, ty = tid >> 4;

    const int b = blockIdx.z, h = blockIdx.y;
    const int it = (int)gridDim.x - 1 - (int)blockIdx.x;  // big tiles first
    const int I0 = it * 64;
    const size_t headOff = (size_t)h * SDIM;
    const float4 f4z = make_float4(0.f, 0.f, 0.f, 0.f);

    // Stage Q tile once, pre-split (hi,lo)
    for (int idx = tid; idx < 1024; idx += 256) {
        int r = idx >> 4, s4 = (idx & 15) << 2;
        float4 v = *(const float4*)&Q[((size_t)(b * TLEN + I0 + r)) * EDIM + headOff + s4];
        float2* p = &Qs2[r * AP + s4];
        p[0] = split2(v.x); p[1] = split2(v.y);
        p[2] = split2(v.z); p[3] = split2(v.w);
    }

    float m_r[4], l_r[4];
    #pragma unroll
    for (int i = 0; i < 4; i++) { m_r[i] = -INFINITY; l_r[i] = 0.f; }
    float o_acc[4][4];
    #pragma unroll
    for (int n = 0; n < 4; n++)
        #pragma unroll
        for (int q = 0; q < 4; q++) o_acc[n][q] = 0.f;

    for (int jt = 0; jt <= it; jt++) {
        const int J0 = jt * 64;
        const int pbase = I0 + J0;

        __syncthreads();   // prev tile's PV / Ssm reads done

        // ---- Stage K (float4), KP band (float4), V natural (float4)
        for (int idx = tid; idx < 1024; idx += 256) {
            int c = idx >> 4, s4 = (idx & 15) << 2;
            *(float4*)&Bs[c * AP + s4] =
                *(const float4*)&Kt[((size_t)(b * TLEN + J0 + c)) * EDIM + headOff + s4];
        }
        for (int idx = tid; idx < 2048; idx += 256) {
            int pl = idx >> 4, s4 = (idx & 15) << 2;
            int p = pbase + pl;
            float4 v = (p < P2) ? *(const float4*)&KP[(size_t)p * EDIM + headOff + s4] : f4z;
            *(float4*)&Bs[(64 + pl) * AP + s4] = v;
        }
        for (int idx = tid; idx < 1024; idx += 256) {
            int j = idx >> 4, s4 = (idx & 15) << 2;
            *(float4*)&Vs[j * VP + s4] =
                *(const float4*)&V[((size_t)(b * TLEN + J0 + j)) * EDIM + headOff + s4];
        }
        if (tid < 64) dpts[tid] = dpt[((size_t)(b * HEADS + h)) * TLEN + J0 + tid];
        if (tid < 128) {
            int p = pbase + tid;
            cpps[tid] = (p < P2) ? cpp[(size_t)h * P2 + p] : 0.f;
        }
        __syncthreads();

        // ---- Scores mma: S[64x192] = Q @ Bs^T (tf32x3, 32x48 per warp) ----
        float sacc[2][6][4];
        #pragma unroll
        for (int mi = 0; mi < 2; mi++)
            #pragma unroll
            for (int n = 0; n < 6; n++)
                #pragma unroll
                for (int q = 0; q < 4; q++) sacc[mi][n][q] = 0.f;

        #pragma unroll
        for (int kk = 0; kk < 64; kk += 8) {
            uint32_t ah[2][4], al[2][4];
            #pragma unroll
            for (int mi = 0; mi < 2; mi++) {
                int r0 = rm + 16 * mi + g;
                uint2 q0 = *(uint2*)&Qs2[r0 * AP + kk + t];
                uint2 q1 = *(uint2*)&Qs2[(r0 + 8) * AP + kk + t];
                uint2 q2 = *(uint2*)&Qs2[r0 * AP + kk + t + 4];
                uint2 q3 = *(uint2*)&Qs2[(r0 + 8) * AP + kk + t + 4];
                ah[mi][0] = q0.x; al[mi][0] = q0.y;
                ah[mi][1] = q1.x; al[mi][1] = q1.y;
                ah[mi][2] = q2.x; al[mi][2] = q2.y;
                ah[mi][3] = q3.x; al[mi][3] = q3.y;
            }
            #pragma unroll
            for (int nt = 0; nt < 6; nt++) {
                int n0 = cn + nt * 8;
                uint32_t bh0, bl0, bh1, bl1;
                msplit(Bs[(n0 + g) * AP + kk + t],     bh0, bl0);
                msplit(Bs[(n0 + g) * AP + kk + t + 4], bh1, bl1);
                #pragma unroll
                for (int mi = 0; mi < 2; mi++)
                    mma_x3(sacc[mi][nt], ah[mi], al[mi], bh0, bh1, bl0, bl1);
            }
        }

        __syncthreads();   // all warps done reading Bs; overwrite as Ssm
        #pragma unroll
        for (int mi = 0; mi < 2; mi++) {
            int r0 = rm + 16 * mi + g;
            #pragma unroll
            for (int nt = 0; nt < 6; nt++) {
                int n0 = cn + nt * 8 + 2 * t;
                Ssm[r0 * SP + n0]           = sacc[mi][nt][0];
                Ssm[r0 * SP + n0 + 1]       = sacc[mi][nt][1];
                Ssm[(r0 + 8) * SP + n0]     = sacc[mi][nt][2];
                Ssm[(r0 + 8) * SP + n0 + 1] = sacc[mi][nt][3];
            }
        }
        __syncthreads();

        // ---- Softmax (fp32 SIMT): P written IN PLACE over S cols 0..63 ----
        #pragma unroll
        for (int i = 0; i < 4; i++) {
            int r = ty + 16 * i;
            float sc[4];
            float mx = -INFINITY;
            #pragma unroll
            for (int j = 0; j < 4; j++) {
                int c = tx + 16 * j;
                float v = Ssm[r * SP + c] + Ssm[r * SP + 64 + r + c]
                        + dpts[c] + cpps[r + c];
                if (J0 + c > I0 + r) v = -1e30f;
                sc[j] = v;
                mx = fmaxf(mx, v);
            }
            #pragma unroll
            for (int off = 8; off >= 1; off >>= 1)
                mx = fmaxf(mx, __shfl_xor_sync(0xffffffffu, mx, off));
            float mnew = fmaxf(m_r[i], mx);
            float scale = __expf(m_r[i] - mnew);
            m_r[i] = mnew;
            float rs = 0.f;
            #pragma unroll
            for (int j = 0; j < 4; j++) {
                float p = __expf(sc[j] - mnew);
                Ssm[r * SP + tx + 16 * j] = p;   // in-place: same slot this thread read
                rs += p;
            }
            #pragma unroll
            for (int off = 8; off >= 1; off >>= 1)
                rs += __shfl_xor_sync(0xffffffffu, rs, off);
            l_r[i] = l_r[i] * scale + rs;
            if (tx == 0) {
                scale_sm[r] = scale;
                lsum_sm[r]  = l_r[i];
            }
        }
        __syncthreads();

        // ---- PV mma: O = O*scale + P @ V (tf32x3, 16x32 per warp) ----
        const float sA = scale_sm[sm0 + g];
        const float sB = scale_sm[sm0 + g + 8];
        #pragma unroll
        for (int nt = 0; nt < 4; nt++) {
            o_acc[nt][0] *= sA; o_acc[nt][1] *= sA;
            o_acc[nt][2] *= sB; o_acc[nt][3] *= sB;
        }
        #pragma unroll
        for (int kk = 0; kk < 64; kk += 8) {
            uint32_t ah[4], al[4];
            msplit(Ssm[(sm0 + g) * SP + kk + t],         ah[0], al[0]);
            msplit(Ssm[(sm0 + g + 8) * SP + kk + t],     ah[1], al[1]);
            msplit(Ssm[(sm0 + g) * SP + kk + t + 4],     ah[2], al[2]);
            msplit(Ssm[(sm0 + g + 8) * SP + kk + t + 4], ah[3], al[3]);
            #pragma unroll
            for (int nt = 0; nt < 4; nt++) {
                int n0 = pn0 + nt * 8;
                uint32_t bh0, bl0, bh1, bl1;
                msplit(Vs[(kk + t) * VP + n0 + g],       bh0, bl0);
                msplit(Vs[(kk + t + 4) * VP + n0 + g],   bh1, bl1);
                mma_x3(o_acc[nt], ah, al, bh0, bh1, bl0, bl1);
            }
        }
    }

    __syncthreads();
    const float invA = 1.f / lsum_sm[sm0 + g];
    const float invB = 1.f / lsum_sm[sm0 + g + 8];
    const size_t row0 = (size_t)(b * TLEN + I0 + sm0 + g) * EDIM;
    const size_t row1 = row0 + 8 * EDIM;
    #pragma unroll
    for (int nt = 0; nt < 4; nt++) {
        size_t col = headOff + pn0 + nt * 8 + 2 * t;
        O[row0 + col]     = o_acc[nt][0] * invA;
        O[row0 + col + 1] = o_acc[nt][1] * invA;
        O[row1 + col]     = o_acc[nt][2] * invB;
        O[row1 + col + 1] = o_acc[nt][3] * invB;
    }
}

// ---------------------------------------------------------------------------
// Launch (5 launches total)
// ---------------------------------------------------------------------------
extern "C" void kernel_launch(void* const* d_in, const int* in_sizes, int n_in,
                              void* d_out, int out_size)
{
    const float* x     = (const float*)d_in[0];
    const float* Wq    = (const float*)d_in[1];
    const float* Wk    = (const float*)d_in[2];
    const float* Wkp   = (const float*)d_in[3];
    const float* Wv    = (const float*)d_in[4];
    const float* Wu    = (const float*)d_in[5];
    const float* bu    = (const float*)d_in[6];
    const float* parma = (const float*)d_in[7];
    const float* parmb = (const float*)d_in[8];
    const float* pos   = (const float*)d_in[9];
    float* out = (float*)d_out;

    float *Qb, *Kb, *Vb, *KPb, *dptb, *cppb, *ATTb, *Wtb;
    cudaGetSymbolAddress((void**)&Qb,   g_Q);
    cudaGetSymbolAddress((void**)&Kb,   g_K);
    cudaGetSymbolAddress((void**)&Vb,   g_V);
    cudaGetSymbolAddress((void**)&KPb,  g_KP);
    cudaGetSymbolAddress((void**)&dptb, g_dpt);
    cudaGetSymbolAddress((void**)&cppb, g_cpp);
    cudaGetSymbolAddress((void**)&ATTb, g_ATT);
    cudaGetSymbolAddress((void**)&Wtb,  g_Wt);

    const size_t WSZ = (size_t)EDIM * EDIM;

    // 1) transpose all 5 weights (g_Wt order: Wq, Wk, Wv, Wkp, Wu)
    transpose5_kernel<<<dim3(32, 32, 5), dim3(32, 8)>>>(Wq, Wk, Wv, Wkp, Wu, Wtb);

    // 2) fused Q/K/V/KP projections (pre-split smem GEMM)
    cudaFuncSetAttribute(fused_gemm_kernel,
                         cudaFuncAttributeMaxDynamicSharedMemorySize,
                         GEMM_SMEM_BYTES);
    fused_gemm_kernel<<<dim3(8, 32, 4), 256, GEMM_SMEM_BYTES>>>(
        x, pos, Wtb, Qb, Kb, Vb, KPb);

    // 3) fused dpt + cpp
    const int total_small = BATCH * HEADS * TLEN + HEADS * P2;
    dptcpp_kernel<<<(total_small + 255) / 256, 256>>>(Kb, KPb, parma, parmb,
                                                      dptb, cppb);

    // 4) attention
    size_t smemBytes = (size_t)ATTN_SMEM_FLOATS * sizeof(float);
    cudaFuncSetAttribute(attn_kernel,
                         cudaFuncAttributeMaxDynamicSharedMemorySize,
                         (int)smemBytes);
    attn_kernel<<<dim3(TLEN / 64, HEADS, BATCH), 256, smemBytes>>>(
        Qb, Kb, Vb, KPb, dptb, cppb, ATTb);

    // 5) output projection (+bias)
    cudaFuncSetAttribute(gemmU_kernel,
                         cudaFuncAttributeMaxDynamicSharedMemorySize,
                         GEMM_SMEM_BYTES);
    gemmU_kernel<<<dim3(8, 32), 256, GEMM_SMEM_BYTES>>>(
        ATTb, Wtb + 4 * WSZ, bu, out);
}

// round 9
// speedup vs baseline: 1.4453x; 1.4453x over previous
#include <cuda_runtime.h>
#include <math.h>
#include <stdint.h>

// Problem constants
#define BATCH 4
#define TLEN  1024
#define EDIM  1024
#define HEADS 16
#define SDIM  64
#define P2    2047   // 2*t - 1

// ---------------------------------------------------------------------------
// Scratch (device globals — no runtime allocation allowed)
// ---------------------------------------------------------------------------
__device__ float g_Q  [(size_t)BATCH * TLEN * EDIM];
__device__ float g_K  [(size_t)BATCH * TLEN * EDIM];
__device__ float g_V  [(size_t)BATCH * TLEN * EDIM];
__device__ float g_KP [(size_t)P2 * EDIM];
__device__ float g_dpt[(size_t)BATCH * HEADS * TLEN];
__device__ float g_cpp[(size_t)HEADS * P2];
__device__ float g_ATT[(size_t)BATCH * TLEN * EDIM];
__device__ float g_Wt [(size_t)5 * EDIM * EDIM];   // transposed weights [N,K]

// ---------------------------------------------------------------------------
// tf32 helpers. Mask split: hi = x with low 13 bits zeroed (tf32-exact),
// lo = x - hi exact in fp32 (Sterbenz).
// ---------------------------------------------------------------------------
__device__ __forceinline__ void msplit(float x, uint32_t& hi, uint32_t& lo) {
    uint32_t h = __float_as_uint(x) & 0xFFFFE000u;
    hi = h;
    lo = __float_as_uint(x - __uint_as_float(h));
}
__device__ __forceinline__ void mma_tf32(float* c,
    uint32_t a0, uint32_t a1, uint32_t a2, uint32_t a3,
    uint32_t b0, uint32_t b1)
{
    asm volatile(
        "mma.sync.aligned.m16n8k8.row.col.f32.tf32.tf32.f32 "
        "{%0,%1,%2,%3}, {%4,%5,%6,%7}, {%8,%9}, {%0,%1,%2,%3};"
        : "+f"(c[0]), "+f"(c[1]), "+f"(c[2]), "+f"(c[3])
        : "r"(a0), "r"(a1), "r"(a2), "r"(a3), "r"(b0), "r"(b1));
}
// x3 compensated: al*bh + ah*bl + ah*bh (residual ~2^-22)
__device__ __forceinline__ void mma_x3(float* c,
    const uint32_t* ah, const uint32_t* al,
    uint32_t bh0, uint32_t bh1, uint32_t bl0, uint32_t bl1)
{
    mma_tf32(c, al[0], al[1], al[2], al[3], bh0, bh1);
    mma_tf32(c, ah[0], ah[1], ah[2], ah[3], bl0, bl1);
    mma_tf32(c, ah[0], ah[1], ah[2], ah[3], bh0, bh1);
}

// cp.async helpers (baseline PTX, sm_80+)
__device__ __forceinline__ void cpa16(void* smem_dst, const void* gsrc, bool v) {
    uint32_t s = (uint32_t)__cvta_generic_to_shared(smem_dst);
    int sz = v ? 16 : 0;
    asm volatile("cp.async.cg.shared.global [%0], [%1], 16, %2;"
                 :: "r"(s), "l"(gsrc), "r"(sz) : "memory");
}
#define CP_COMMIT() asm volatile("cp.async.commit_group;" ::: "memory")
#define CP_WAIT1()  asm volatile("cp.async.wait_group 1;" ::: "memory")
#define CP_WAIT0()  asm volatile("cp.async.wait_group 0;" ::: "memory")

// ---------------------------------------------------------------------------
// Batched weight transpose: dst[z][N,K] = src_z[K,N], 1024x1024 x5
// ---------------------------------------------------------------------------
__global__ void __launch_bounds__(256) transpose5_kernel(
    const float* __restrict__ W0, const float* __restrict__ W1,
    const float* __restrict__ W2, const float* __restrict__ W3,
    const float* __restrict__ W4, float* __restrict__ dstBase)
{
    __shared__ float t[32][33];
    int z = blockIdx.z;
    const float* src = (z == 0) ? W0 : (z == 1) ? W1 : (z == 2) ? W2
                     : (z == 3) ? W3 : W4;
    float* dst = dstBase + (size_t)z * EDIM * EDIM;
    int bx = blockIdx.x * 32, by = blockIdx.y * 32;
    int x = threadIdx.x, y = threadIdx.y;   // block (32, 8)
    #pragma unroll
    for (int i = 0; i < 32; i += 8)
        t[y + i][x] = src[(size_t)(by + y + i) * EDIM + bx + x];
    __syncthreads();
    #pragma unroll
    for (int i = 0; i < 32; i += 8)
        dst[(size_t)(bx + y + i) * EDIM + by + x] = t[x][y + i];
}

// ---------------------------------------------------------------------------
// Tensor-core GEMM tile body (tf32x3): C[bm:+128, bn:+128] = A @ Bt^T (+bias)
// BK=32, 256 threads (8 warps: 64m x 32n each), m16n8k8 x3 compensation.
// cp.async double-buffered staging (one k-tile prefetch depth).
// ---------------------------------------------------------------------------
#define PADK 36
#define GTILE (128 * PADK)                    // floats per matrix buffer
#define GEMM_SMEM_BYTES (4 * GTILE * 4)       // 2 bufs x (A + B) = 73728 B

__device__ __forceinline__ void gemm_stage(
    float* As, float* Bs,
    const float* __restrict__ A, const float* __restrict__ Bt,
    int M, int bm, int bn, int koff, int tid)
{
    #pragma unroll
    for (int r = 0; r < 4; r++) {
        int slot = tid + 256 * r;
        int row = slot >> 3, kc = (slot & 7) * 4;
        int grow = bm + row;
        bool v = grow < M;
        const float* ga = &A[(size_t)(v ? grow : 0) * EDIM + koff + kc];
        cpa16(&As[row * PADK + kc], ga, v);
        cpa16(&Bs[row * PADK + kc],
              &Bt[(size_t)(bn + row) * EDIM + koff + kc], true);
    }
    CP_COMMIT();
}

__device__ __forceinline__ void gemm_tile(
    const float* __restrict__ A, const float* __restrict__ Bt,
    const float* __restrict__ bias, float* __restrict__ C,
    int M, int hasBias, int bm, int bn)
{
    extern __shared__ float gsm[];
    float* Ab[2] = { gsm,             gsm + GTILE };
    float* Bb[2] = { gsm + 2 * GTILE, gsm + 3 * GTILE };

    const int tid  = threadIdx.x;
    const int wid  = tid >> 5;
    const int lane = tid & 31;
    const int wm = wid & 1;          // 0..1 : 64-row slice
    const int wn = wid >> 1;         // 0..3 : 32-col slice
    const int g = lane >> 2;         // group id 0..7
    const int t = lane & 3;          // thread-in-group 0..3

    gemm_stage(Ab[0], Bb[0], A, Bt, M, bm, bn, 0,  tid);
    gemm_stage(Ab[1], Bb[1], A, Bt, M, bm, bn, 32, tid);

    float acc[4][4][4];
    #pragma unroll
    for (int mi = 0; mi < 4; mi++)
        #pragma unroll
        for (int ni = 0; ni < 4; ni++)
            #pragma unroll
            for (int q = 0; q < 4; q++) acc[mi][ni][q] = 0.f;

    #pragma unroll 1
    for (int kt = 0; kt < 32; kt++) {
        if (kt + 1 < 32) CP_WAIT1(); else CP_WAIT0();
        __syncthreads();
        const float* As = Ab[kt & 1];
        const float* Bs = Bb[kt & 1];

        #pragma unroll
        for (int kk = 0; kk < 32; kk += 8) {
            uint32_t ah[4][4], al[4][4], bh[4][2], bl[4][2];
            #pragma unroll
            for (int mi = 0; mi < 4; mi++) {
                int r0 = wm * 64 + mi * 16 + g;
                int c0 = kk + t;
                msplit(As[r0 * PADK + c0],           ah[mi][0], al[mi][0]);
                msplit(As[(r0 + 8) * PADK + c0],     ah[mi][1], al[mi][1]);
                msplit(As[r0 * PADK + c0 + 4],       ah[mi][2], al[mi][2]);
                msplit(As[(r0 + 8) * PADK + c0 + 4], ah[mi][3], al[mi][3]);
            }
            #pragma unroll
            for (int ni = 0; ni < 4; ni++) {
                int rn = wn * 32 + ni * 8 + g;
                msplit(Bs[rn * PADK + kk + t],     bh[ni][0], bl[ni][0]);
                msplit(Bs[rn * PADK + kk + t + 4], bh[ni][1], bl[ni][1]);
            }
            #pragma unroll
            for (int mi = 0; mi < 4; mi++)
                #pragma unroll
                for (int ni = 0; ni < 4; ni++)
                    mma_x3(acc[mi][ni], ah[mi], al[mi],
                           bh[ni][0], bh[ni][1], bl[ni][0], bl[ni][1]);
        }
        __syncthreads();
        if (kt + 2 < 32)
            gemm_stage(Ab[kt & 1], Bb[kt & 1], A, Bt, M, bm, bn,
                       (kt + 2) * 32, tid);
    }

    #pragma unroll
    for (int mi = 0; mi < 4; mi++) {
        int row0 = bm + wm * 64 + mi * 16 + g;
        #pragma unroll
        for (int ni = 0; ni < 4; ni++) {
            int col = bn + wn * 32 + ni * 8 + t * 2;
            float b0 = hasBias ? bias[col] : 0.f;
            float b1 = hasBias ? bias[col + 1] : 0.f;
            if (row0 < M) {
                C[(size_t)row0 * EDIM + col]     = acc[mi][ni][0] + b0;
                C[(size_t)row0 * EDIM + col + 1] = acc[mi][ni][1] + b1;
            }
            if (row0 + 8 < M) {
                C[(size_t)(row0 + 8) * EDIM + col]     = acc[mi][ni][2] + b0;
                C[(size_t)(row0 + 8) * EDIM + col + 1] = acc[mi][ni][3] + b1;
            }
        }
    }
}

// Fused projections: z=0..2 -> Q/K/V from x; z=3 -> KP from pos_emb.
__global__ void __launch_bounds__(256, 2) fused_gemm_kernel(
    const float* __restrict__ x, const float* __restrict__ pos,
    const float* __restrict__ Wt0,
    float* __restrict__ Qb, float* __restrict__ Kb,
    float* __restrict__ Vb, float* __restrict__ KPb)
{
    const int z = blockIdx.z;
    const float* A = (z < 3) ? x : pos;
    const int M = (z < 3) ? (BATCH * TLEN) : P2;
    const int bm = blockIdx.y * 128;
    if (bm >= M) return;
    const float* Bt = Wt0 + (size_t)z * EDIM * EDIM;
    float* C = (z == 0) ? Qb : (z == 1) ? Kb : (z == 2) ? Vb : KPb;
    gemm_tile(A, Bt, nullptr, C, M, 0, bm, blockIdx.x * 128);
}

__global__ void __launch_bounds__(256, 2) gemmU_kernel(
    const float* __restrict__ A, const float* __restrict__ Bt,
    const float* __restrict__ bias, float* __restrict__ C)
{
    gemm_tile(A, Bt, bias, C, BATCH * TLEN, 1, blockIdx.y * 128, blockIdx.x * 128);
}

// ---------------------------------------------------------------------------
// Fused dpt + cpp
// ---------------------------------------------------------------------------
__global__ void __launch_bounds__(256) dptcpp_kernel(
    const float* __restrict__ Kt, const float* __restrict__ KP,
    const float* __restrict__ parma, const float* __restrict__ parmb,
    float* __restrict__ dpt, float* __restrict__ cpp)
{
    int idx = blockIdx.x * 256 + threadIdx.x;
    if (idx < BATCH * HEADS * TLEN) {
        int j = idx & (TLEN - 1);
        int h = (idx >> 10) & (HEADS - 1);
        int b = idx >> 14;
        const float* kr = Kt + ((size_t)(b * TLEN + j)) * EDIM + h * SDIM;
        const float* pa = parma + h * SDIM;
        float s = 0.f;
        #pragma unroll
        for (int ss = 0; ss < SDIM; ss++) s = fmaf(pa[ss], kr[ss], s);
        dpt[idx] = s;
    } else {
        int i2 = idx - BATCH * HEADS * TLEN;
        if (i2 >= HEADS * P2) return;
        int h = i2 / P2;
        int p = i2 - h * P2;
        const float* kr = KP + (size_t)p * EDIM + h * SDIM;
        const float* pb = parmb + h * SDIM;
        float s = 0.f;
        #pragma unroll
        for (int ss = 0; ss < SDIM; ss++) s = fmaf(pb[ss], kr[ss], s);
        cpp[i2] = s;
    }
}

// ---------------------------------------------------------------------------
// Tensor-core attention (round-7 structure; V stored NATURALLY, stride 72 —
// removes the 8-way STS conflict of the transposed Vt staging).
// One CTA per (b,h,64-row i-tile), 256 threads.
// Scores warps: 2m x 4n (32x48); PV warps: 4m x 2n (16x32).
// ---------------------------------------------------------------------------
#define AP 68    // padded stride (conflict-free fragment reads: 4g+t)
#define VP 72    // V natural stride: banks 8t+g for PV reads, conflict-free
#define SP 196   // S matrix stride (64 rows x 192 cols)

#define ATTN_SMEM_FLOATS (64*AP + 192*AP + 64*VP + 64*AP + 64 + 128 + 64 + 64)

__global__ void __launch_bounds__(256, 2) attn_kernel(
    const float* __restrict__ Q, const float* __restrict__ Kt,
    const float* __restrict__ V, const float* __restrict__ KP,
    const float* __restrict__ dpt, const float* __restrict__ cpp,
    float* __restrict__ O)
{
    extern __shared__ float sm[];
    float* Qs   = sm;                   // [64][AP]  Q rows (A frag source)
    float* Bs   = Qs + 64 * AP;         // [192][AP] rows 0..63 = K, 64..191 = KP band
    float* Ssm  = Bs;                   // [64][SP]  aliases Bs after scores mma
    float* Vs   = Bs + 192 * AP;        // [64][VP]  NATURAL: Vs[j][s]
    float* Psm  = Vs + 64 * VP;         // [64][AP]
    float* dpts = Psm + 64 * AP;        // [64]
    float* cpps = dpts + 64;            // [128]
    float* scale_sm = cpps + 128;       // [64]
    float* lsum_sm  = scale_sm + 64;    // [64]

    const int tid  = threadIdx.x;
    const int lane = tid & 31;
    const int wid  = tid >> 5;
    const int g = lane >> 2;            // 0..7
    const int t = lane & 3;             // 0..3
    const int rm = (wid & 1) * 32;      // scores m-base (32-row slice)
    const int cn = (wid >> 1) * 48;     // scores n-base (48-col slice)
    const int sm0 = (wid & 3) * 16;     // PV m-slice
    const int pn0 = (wid >> 2) * 32;    // PV n-slice
    const int tx = tid & 15, ty = tid >> 4;

    const int b = blockIdx.z, h = blockIdx.y;
    const int it = (int)gridDim.x - 1 - (int)blockIdx.x;  // big tiles first
    const int I0 = it * 64;
    const size_t headOff = (size_t)h * SDIM;
    const float4 f4z = make_float4(0.f, 0.f, 0.f, 0.f);

    // Stage Q tile once (float4)
    for (int idx = tid; idx < 1024; idx += 256) {
        int r = idx >> 4, s4 = (idx & 15) << 2;
        *(float4*)&Qs[r * AP + s4] =
            *(const float4*)&Q[((size_t)(b * TLEN + I0 + r)) * EDIM + headOff + s4];
    }

    float m_r[4], l_r[4];
    #pragma unroll
    for (int i = 0; i < 4; i++) { m_r[i] = -INFINITY; l_r[i] = 0.f; }
    float o_acc[4][4];
    #pragma unroll
    for (int n = 0; n < 4; n++)
        #pragma unroll
        for (int q = 0; q < 4; q++) o_acc[n][q] = 0.f;

    for (int jt = 0; jt <= it; jt++) {
        const int J0 = jt * 64;
        const int pbase = I0 + J0;

        __syncthreads();   // prev tile's PV / Ssm reads done

        // ---- Stage K (float4), KP band (float4), V natural (float4)
        for (int idx = tid; idx < 1024; idx += 256) {
            int c = idx >> 4, s4 = (idx & 15) << 2;
            *(float4*)&Bs[c * AP + s4] =
                *(const float4*)&Kt[((size_t)(b * TLEN + J0 + c)) * EDIM + headOff + s4];
        }
        for (int idx = tid; idx < 2048; idx += 256) {
            int pl = idx >> 4, s4 = (idx & 15) << 2;
            int p = pbase + pl;
            float4 v = (p < P2) ? *(const float4*)&KP[(size_t)p * EDIM + headOff + s4] : f4z;
            *(float4*)&Bs[(64 + pl) * AP + s4] = v;
        }
        for (int idx = tid; idx < 1024; idx += 256) {
            int j = idx >> 4, s4 = (idx & 15) << 2;
            *(float4*)&Vs[j * VP + s4] =
                *(const float4*)&V[((size_t)(b * TLEN + J0 + j)) * EDIM + headOff + s4];
        }
        if (tid < 64) dpts[tid] = dpt[((size_t)(b * HEADS + h)) * TLEN + J0 + tid];
        if (tid < 128) {
            int p = pbase + tid;
            cpps[tid] = (p < P2) ? cpp[(size_t)h * P2 + p] : 0.f;
        }
        __syncthreads();

        // ---- Scores mma: S[64x192] = Q @ Bs^T (tf32x3, 32x48 per warp) ----
        float sacc[2][6][4];
        #pragma unroll
        for (int mi = 0; mi < 2; mi++)
            #pragma unroll
            for (int n = 0; n < 6; n++)
                #pragma unroll
                for (int q = 0; q < 4; q++) sacc[mi][n][q] = 0.f;

        #pragma unroll
        for (int kk = 0; kk < 64; kk += 8) {
            uint32_t ah[2][4], al[2][4];
            #pragma unroll
            for (int mi = 0; mi < 2; mi++) {
                int r0 = rm + 16 * mi + g;
                msplit(Qs[r0 * AP + kk + t],           ah[mi][0], al[mi][0]);
                msplit(Qs[(r0 + 8) * AP + kk + t],     ah[mi][1], al[mi][1]);
                msplit(Qs[r0 * AP + kk + t + 4],       ah[mi][2], al[mi][2]);
                msplit(Qs[(r0 + 8) * AP + kk + t + 4], ah[mi][3], al[mi][3]);
            }
            #pragma unroll
            for (int nt = 0; nt < 6; nt++) {
                int n0 = cn + nt * 8;
                uint32_t bh0, bl0, bh1, bl1;
                msplit(Bs[(n0 + g) * AP + kk + t],     bh0, bl0);
                msplit(Bs[(n0 + g) * AP + kk + t + 4], bh1, bl1);
                #pragma unroll
                for (int mi = 0; mi < 2; mi++)
                    mma_x3(sacc[mi][nt], ah[mi], al[mi], bh0, bh1, bl0, bl1);
            }
        }

        __syncthreads();   // all warps done reading Bs; overwrite as Ssm
        #pragma unroll
        for (int mi = 0; mi < 2; mi++) {
            int r0 = rm + 16 * mi + g;
            #pragma unroll
            for (int nt = 0; nt < 6; nt++) {
                int n0 = cn + nt * 8 + 2 * t;
                Ssm[r0 * SP + n0]           = sacc[mi][nt][0];
                Ssm[r0 * SP + n0 + 1]       = sacc[mi][nt][1];
                Ssm[(r0 + 8) * SP + n0]     = sacc[mi][nt][2];
                Ssm[(r0 + 8) * SP + n0 + 1] = sacc[mi][nt][3];
            }
        }
        __syncthreads();

        // ---- Softmax (fp32 SIMT): rows ty+16i, cols tx+16j ----
        #pragma unroll
        for (int i = 0; i < 4; i++) {
            int r = ty + 16 * i;
            float sc[4];
            float mx = -INFINITY;
            #pragma unroll
            for (int j = 0; j < 4; j++) {
                int c = tx + 16 * j;
                float v = Ssm[r * SP + c] + Ssm[r * SP + 64 + r + c]
                        + dpts[c] + cpps[r + c];
                if (J0 + c > I0 + r) v = -1e30f;
                sc[j] = v;
                mx = fmaxf(mx, v);
            }
            #pragma unroll
            for (int off = 8; off >= 1; off >>= 1)
                mx = fmaxf(mx, __shfl_xor_sync(0xffffffffu, mx, off));
            float mnew = fmaxf(m_r[i], mx);
            float scale = __expf(m_r[i] - mnew);
            m_r[i] = mnew;
            float rs = 0.f;
            #pragma unroll
            for (int j = 0; j < 4; j++) {
                float p = __expf(sc[j] - mnew);
                Psm[r * AP + tx + 16 * j] = p;
                rs += p;
            }
            #pragma unroll
            for (int off = 8; off >= 1; off >>= 1)
                rs += __shfl_xor_sync(0xffffffffu, rs, off);
            l_r[i] = l_r[i] * scale + rs;
            if (tx == 0) {
                scale_sm[r] = scale;
                lsum_sm[r]  = l_r[i];
            }
        }
        __syncthreads();

        // ---- PV mma: O = O*scale + P @ V (tf32x3, 16x32 per warp) ----
        const float sA = scale_sm[sm0 + g];
        const float sB = scale_sm[sm0 + g + 8];
        #pragma unroll
        for (int nt = 0; nt < 4; nt++) {
            o_acc[nt][0] *= sA; o_acc[nt][1] *= sA;
            o_acc[nt][2] *= sB; o_acc[nt][3] *= sB;
        }
        #pragma unroll
        for (int kk = 0; kk < 64; kk += 8) {
            uint32_t ah[4], al[4];
            msplit(Psm[(sm0 + g) * AP + kk + t],         ah[0], al[0]);
            msplit(Psm[(sm0 + g + 8) * AP + kk + t],     ah[1], al[1]);
            msplit(Psm[(sm0 + g) * AP + kk + t + 4],     ah[2], al[2]);
            msplit(Psm[(sm0 + g + 8) * AP + kk + t + 4], ah[3], al[3]);
            #pragma unroll
            for (int nt = 0; nt < 4; nt++) {
                int n0 = pn0 + nt * 8;
                uint32_t bh0, bl0, bh1, bl1;
                msplit(Vs[(kk + t) * VP + n0 + g],     bh0, bl0);
                msplit(Vs[(kk + t + 4) * VP + n0 + g], bh1, bl1);
                mma_x3(o_acc[nt], ah, al, bh0, bh1, bl0, bl1);
            }
        }
    }

    __syncthreads();
    const float invA = 1.f / lsum_sm[sm0 + g];
    const float invB = 1.f / lsum_sm[sm0 + g + 8];
    const size_t row0 = (size_t)(b * TLEN + I0 + sm0 + g) * EDIM;
    const size_t row1 = row0 + 8 * EDIM;
    #pragma unroll
    for (int nt = 0; nt < 4; nt++) {
        size_t col = headOff + pn0 + nt * 8 + 2 * t;
        O[row0 + col]     = o_acc[nt][0] * invA;
        O[row0 + col + 1] = o_acc[nt][1] * invA;
        O[row1 + col]     = o_acc[nt][2] * invB;
        O[row1 + col + 1] = o_acc[nt][3] * invB;
    }
}

// ---------------------------------------------------------------------------
// Launch (5 launches total)
// ---------------------------------------------------------------------------
extern "C" void kernel_launch(void* const* d_in, const int* in_sizes, int n_in,
                              void* d_out, int out_size)
{
    const float* x     = (const float*)d_in[0];
    const float* Wq    = (const float*)d_in[1];
    const float* Wk    = (const float*)d_in[2];
    const float* Wkp   = (const float*)d_in[3];
    const float* Wv    = (const float*)d_in[4];
    const float* Wu    = (const float*)d_in[5];
    const float* bu    = (const float*)d_in[6];
    const float* parma = (const float*)d_in[7];
    const float* parmb = (const float*)d_in[8];
    const float* pos   = (const float*)d_in[9];
    float* out = (float*)d_out;

    float *Qb, *Kb, *Vb, *KPb, *dptb, *cppb, *ATTb, *Wtb;
    cudaGetSymbolAddress((void**)&Qb,   g_Q);
    cudaGetSymbolAddress((void**)&Kb,   g_K);
    cudaGetSymbolAddress((void**)&Vb,   g_V);
    cudaGetSymbolAddress((void**)&KPb,  g_KP);
    cudaGetSymbolAddress((void**)&dptb, g_dpt);
    cudaGetSymbolAddress((void**)&cppb, g_cpp);
    cudaGetSymbolAddress((void**)&ATTb, g_ATT);
    cudaGetSymbolAddress((void**)&Wtb,  g_Wt);

    const size_t WSZ = (size_t)EDIM * EDIM;

    // 1) transpose all 5 weights (g_Wt order: Wq, Wk, Wv, Wkp, Wu)
    transpose5_kernel<<<dim3(32, 32, 5), dim3(32, 8)>>>(Wq, Wk, Wv, Wkp, Wu, Wtb);

    // 2) fused Q/K/V/KP projections (cp.async double-buffered GEMM)
    cudaFuncSetAttribute(fused_gemm_kernel,
                         cudaFuncAttributeMaxDynamicSharedMemorySize,
                         GEMM_SMEM_BYTES);
    fused_gemm_kernel<<<dim3(8, 32, 4), 256, GEMM_SMEM_BYTES>>>(
        x, pos, Wtb, Qb, Kb, Vb, KPb);

    // 3) fused dpt + cpp
    const int total_small = BATCH * HEADS * TLEN + HEADS * P2;
    dptcpp_kernel<<<(total_small + 255) / 256, 256>>>(Kb, KPb, parma, parmb,
                                                      dptb, cppb);

    // 4) attention
    size_t smemBytes = (size_t)ATTN_SMEM_FLOATS * sizeof(float);
    cudaFuncSetAttribute(attn_kernel,
                         cudaFuncAttributeMaxDynamicSharedMemorySize,
                         (int)smemBytes);
    attn_kernel<<<dim3(TLEN / 64, HEADS, BATCH), 256, smemBytes>>>(
        Qb, Kb, Vb, KPb, dptb, cppb, ATTb);

    // 5) output projection (+bias)
    cudaFuncSetAttribute(gemmU_kernel,
                         cudaFuncAttributeMaxDynamicSharedMemorySize,
                         GEMM_SMEM_BYTES);
    gemmU_kernel<<<dim3(8, 32), 256, GEMM_SMEM_BYTES>>>(
        ATTb, Wtb + 4 * WSZ, bu, out);
}